// round 8
// baseline (speedup 1.0000x reference)
#include <cuda_runtime.h>
#include <cstdint>
#include <cstddef>

#define NNODES 50000
#define NEDGES 800000
#define NTYPES 3
#define DIM    64
#define EPSLN  1e-5f
#define EPC    128              // edges per CTA (divides 800000)

typedef unsigned long long ull;

// ---------------- device scratch -------------------------------------------
__device__ __align__(16) float g_A[(size_t)NTYPES * NNODES * DIM];
__device__ __align__(16) float g_B[(size_t)NTYPES * NNODES * DIM];
__device__ __align__(16) float g_acc[(size_t)NTYPES * NNODES * DIM];
__device__ __align__(8)  int2  g_idx[(size_t)NTYPES * NEDGES];   // {src,dst}
__device__ int   g_deg[NTYPES * NNODES];
__device__ float g_sum[NTYPES * DIM];
__device__ float g_sq[NTYPES * DIM];
__device__ float g_s[NTYPES * DIM];
__device__ float g_c[NTYPES * DIM];
__device__ int   g_is64;

// fast ELU: |err| <= ~5e-7 absolute, fine vs 1e-3 rel_err budget
__device__ __forceinline__ float elu(float x) {
    return x > 0.f ? x : (__expf(x) - 1.f);
}

// ---------------- edge-index dtype detection --------------------------------
__global__ void k_detect(const int* __restrict__ e) {
    if (threadIdx.x == 0 && blockIdx.x == 0) {
        int is64 = 1;
        for (int i = 1; i < 256; i += 2)
            if (e[i] != 0) { is64 = 0; break; }
        g_is64 = is64;
    }
}

// ---------------- index conversion: (src,dst) -> packed int2 -----------------
__global__ void __launch_bounds__(256) k_convert(const void* __restrict__ esrc_raw,
                                                 const void* __restrict__ edst_raw) {
    const size_t i = (size_t)blockIdx.x * 256 + threadIdx.x;
    if (i >= (size_t)NTYPES * NEDGES) return;
    int s, d;
    if (g_is64) {
        s = (int)((const long long*)esrc_raw)[i];
        d = (int)((const long long*)edst_raw)[i];
    } else {
        s = ((const int*)esrc_raw)[i];
        d = ((const int*)edst_raw)[i];
    }
    g_idx[i] = make_int2(s, d);
}

// ---------------- zero-init --------------------------------------------------
__global__ void k_zero() {
    size_t stride = (size_t)gridDim.x * blockDim.x;
    size_t i = (size_t)blockIdx.x * blockDim.x + threadIdx.x;
    float4 z = make_float4(0.f, 0.f, 0.f, 0.f);
    float4* a4 = reinterpret_cast<float4*>(g_acc);
    size_t n4 = (size_t)NTYPES * NNODES * DIM / 4;
    for (size_t k = i; k < n4; k += stride) a4[k] = z;
    for (size_t k = i; k < (size_t)NTYPES * NNODES; k += stride) g_deg[k] = 0;
    if (i < NTYPES * DIM) { g_sum[i] = 0.f; g_sq[i] = 0.f; }
}

// ---------------- per-node precompute (vectorized loads/stores) --------------
__global__ void __launch_bounds__(256) k_pre(const float* __restrict__ F,
                                             const float* __restrict__ W1,
                                             const float* __restrict__ b1) {
    __shared__ float Fs[64 * 68];   // pad 68: 16B-aligned float4 rows
    __shared__ float Ws[64 * 64];
    const int tid = threadIdx.x;
    const int t = blockIdx.y;
    const int half = blockIdx.z;

    const float* Wsrc = W1 + ((size_t)t * 128 + (size_t)half * 64) * 64;
    for (int i = tid; i < 1024; i += 256)
        reinterpret_cast<float4*>(Ws)[i] = reinterpret_cast<const float4*>(Wsrc)[i];

    const int nl = tid >> 2, q = tid & 3;
    const int n = blockIdx.x * 64 + nl;
    {
        const int nc = (n < NNODES) ? n : (NNODES - 1);
        const float4* fr = reinterpret_cast<const float4*>(F + (size_t)nc * DIM + q * 16);
        const float mask = (n < NNODES) ? 1.f : 0.f;
#pragma unroll
        for (int i = 0; i < 4; i++) {
            float4 v = fr[i];
            v.x *= mask; v.y *= mask; v.z *= mask; v.w *= mask;
            *reinterpret_cast<float4*>(&Fs[nl * 68 + q * 16 + i * 4]) = v;
        }
    }
    __syncthreads();

    const int ng = (tid >> 4) << 2;
    const int og = (tid & 15) << 2;
    float acc[4][4] = {};
#pragma unroll 16
    for (int k = 0; k < 64; k++) {
        float a[4];
#pragma unroll
        for (int i = 0; i < 4; i++) a[i] = Fs[(ng + i) * 68 + k];
        float4 w = *reinterpret_cast<const float4*>(&Ws[k * 64 + og]);
        const float wa[4] = {w.x, w.y, w.z, w.w};
#pragma unroll
        for (int i = 0; i < 4; i++)
#pragma unroll
            for (int j = 0; j < 4; j++) acc[i][j] += a[i] * wa[j];
    }

    float bb[4] = {0.f, 0.f, 0.f, 0.f};
    if (half == 0) {
        float4 bv = *reinterpret_cast<const float4*>(&b1[t * DIM + og]);
        bb[0] = bv.x; bb[1] = bv.y; bb[2] = bv.z; bb[3] = bv.w;
    }
    float* dst = (half ? g_B : g_A);
#pragma unroll
    for (int i = 0; i < 4; i++) {
        int nn = blockIdx.x * 64 + ng + i;
        if (nn < NNODES) {
            float4 r = make_float4(acc[i][0] + bb[0], acc[i][1] + bb[1],
                                   acc[i][2] + bb[2], acc[i][3] + bb[3]);
            *reinterpret_cast<float4*>(
                &dst[(((size_t)t * NNODES + nn) << 6) + og]) = r;
        }
    }
}

// ---------------- main edge kernel -------------------------------------------
// 128 edges / CTA, 256 threads, target 3 CTAs/SM. smem (bytes):
//   hnT   float[64][128]  (col = e ^ (q<<3) swizzle)         0      32768
//   W2dup ull, 64 rows x 8 chunks of 10 ull ({w,w} pairs)    32768  40960
//   dsts  int[128]                                           73728  512
//   lng/lnb/b2/ssum/ssq float[64] each                       74240..
extern __shared__ char smem_raw[];

#define SM_HNT   ((float*)smem_raw)
#define SM_W2D   ((ull*)(smem_raw + 32768))
#define SM_DSTS  ((int*)(smem_raw + 73728))
#define SM_LNG   ((float*)(smem_raw + 74240))
#define SM_LNB   ((float*)(smem_raw + 74496))
#define SM_B2    ((float*)(smem_raw + 74752))
#define SM_SSUM  ((float*)(smem_raw + 75008))
#define SM_SSQ   ((float*)(smem_raw + 75264))
#define SMEM_BYTES 75520

__global__ void __launch_bounds__(256, 3) k_edge(const float* __restrict__ lng,
                                                 const float* __restrict__ lnb,
                                                 const float* __restrict__ W2,
                                                 const float* __restrict__ b2) {
    const int tid = threadIdx.x;
    const int t = blockIdx.y;

    // prologue: W2 -> duplicated pairs in bank-spread chunks; affine params
    {
        const float* W2p = W2 + (size_t)t * 64 * 64;
        for (int i = tid; i < 4096; i += 256) {
            const int k = i >> 6, o = i & 63;
            const int og = o >> 3, j = o & 7;
            const float wv = W2p[k * 64 + o];
            const ull d = ((ull)__float_as_uint(wv) << 32) | __float_as_uint(wv);
            SM_W2D[k * 80 + og * 10 + j] = d;
        }
        if (tid < 64) {
            SM_LNG[tid] = lng[t * DIM + tid];
            SM_LNB[tid] = lnb[t * DIM + tid];
            SM_B2[tid]  = b2[t * DIM + tid];
            SM_SSUM[tid] = 0.f; SM_SSQ[tid] = 0.f;
        }
    }
    __syncthreads();

    // ---------- phase A: gather + ELU + LayerNorm, 2 batches of 64 edges ----
    const int el = tid >> 2, q = tid & 3;

    int2 eidx[2];
    {
        const size_t off0 = (size_t)t * NEDGES + (size_t)blockIdx.x * EPC + el;
#pragma unroll
        for (int b = 0; b < 2; b++) eidx[b] = g_idx[off0 + b * 64];
    }

#pragma unroll
    for (int batch = 0; batch < 2; batch++) {
        const int e_loc = batch * 64 + el;
        const int src = eidx[batch].x;
        const int dst = eidx[batch].y;

        float4 av[4], bv[4];
        {
            const float4* ap = reinterpret_cast<const float4*>(
                g_A + (((size_t)t * NNODES + (size_t)src) << 6) + q * 16);
            const float4* bp = reinterpret_cast<const float4*>(
                g_B + (((size_t)t * NNODES + (size_t)dst) << 6) + q * 16);
#pragma unroll
            for (int i = 0; i < 4; i++) av[i] = ap[i];
#pragma unroll
            for (int i = 0; i < 4; i++) bv[i] = bp[i];
        }

        float h[16];
        float sm = 0.f, sq = 0.f;
#pragma unroll
        for (int i = 0; i < 4; i++) {
            float v0 = elu(av[i].x + bv[i].x), v1 = elu(av[i].y + bv[i].y);
            float v2 = elu(av[i].z + bv[i].z), v3 = elu(av[i].w + bv[i].w);
            h[i * 4 + 0] = v0; h[i * 4 + 1] = v1;
            h[i * 4 + 2] = v2; h[i * 4 + 3] = v3;
            sm += v0 + v1 + v2 + v3;
            sq += v0 * v0 + v1 * v1 + v2 * v2 + v3 * v3;
        }

        sm += __shfl_xor_sync(0xffffffffu, sm, 1);
        sq += __shfl_xor_sync(0xffffffffu, sq, 1);
        sm += __shfl_xor_sync(0xffffffffu, sm, 2);
        sq += __shfl_xor_sync(0xffffffffu, sq, 2);
        const float mu = sm * (1.f / 64.f);
        const float var = sq * (1.f / 64.f) - mu * mu;
        const float rstd = rsqrtf(var + EPSLN);

        const int col = e_loc ^ (q << 3);     // XOR swizzle on bits 3..4
#pragma unroll
        for (int i = 0; i < 16; i++) {
            const int ch = q * 16 + i;
            SM_HNT[ch * 128 + col] = (h[i] - mu) * rstd * SM_LNG[ch] + SM_LNB[ch];
        }
        if (q == 0) SM_DSTS[e_loc] = dst;
    }
    __syncthreads();

    // ---------- phase B: P = hn @ W2, FFMA2, 4 edges x 8 outs / thread -------
    const int lane = tid & 31;
    const int eg = lane >> 3;             // 0..3 : edge group within warp
    const int og = lane & 7;              // 0..7 : out group
    const int ebase = (tid >> 5) * 16 + eg * 4;
    const int obase = og * 8;

    ull acc[2][8];
#pragma unroll
    for (int p = 0; p < 2; p++)
#pragma unroll
        for (int o = 0; o < 8; o++) acc[p][o] = 0ull;

#pragma unroll
    for (int q4 = 0; q4 < 4; q4++) {
        const float* hp = SM_HNT + (q4 * 16) * 128 + (ebase ^ (q4 << 3));
        const ull* wp = SM_W2D + (q4 * 16) * 80 + og * 10;
#pragma unroll 4
        for (int i = 0; i < 16; i++) {
            ulonglong2 h01 = *reinterpret_cast<const ulonglong2*>(hp);
            hp += 128;
            const ull av2[2] = {h01.x, h01.y};
            ulonglong2 w01 = *reinterpret_cast<const ulonglong2*>(wp + 0);
            ulonglong2 w23 = *reinterpret_cast<const ulonglong2*>(wp + 2);
            ulonglong2 w45 = *reinterpret_cast<const ulonglong2*>(wp + 4);
            ulonglong2 w67 = *reinterpret_cast<const ulonglong2*>(wp + 6);
            wp += 80;
            const ull wv[8] = {w01.x, w01.y, w23.x, w23.y,
                               w45.x, w45.y, w67.x, w67.y};
#pragma unroll
            for (int p = 0; p < 2; p++)
#pragma unroll
                for (int o = 0; o < 8; o++)
                    asm("fma.rn.f32x2 %0, %1, %2, %0;"
                        : "+l"(acc[p][o]) : "l"(av2[p]), "l"(wv[o]));
        }
    }

    // ---------- phase C: bias + ELU + scatter + BN stats ---------------------
    float bb[8];
#pragma unroll
    for (int o = 0; o < 8; o++) bb[o] = SM_B2[obase + o];

    float cs[8], cq[8];
#pragma unroll
    for (int o = 0; o < 8; o++) { cs[o] = 0.f; cq[o] = 0.f; }

#pragma unroll
    for (int p = 0; p < 2; p++) {
        const int d0 = SM_DSTS[ebase + p * 2 + 0];
        const int d1 = SM_DSTS[ebase + p * 2 + 1];
        float v0[8], v1[8];
#pragma unroll
        for (int o = 0; o < 8; o++) {
            const float2 pv = *reinterpret_cast<const float2*>(&acc[p][o]);
            const float a0 = elu(pv.x + bb[o]);
            const float a1 = elu(pv.y + bb[o]);
            v0[o] = a0; v1[o] = a1;
            cs[o] += a0 + a1;
            cq[o] += a0 * a0 + a1 * a1;
        }
        float* ad0 = g_acc + (((size_t)t * NNODES + d0) << 6) + obase;
        asm volatile("red.global.add.v4.f32 [%0], {%1,%2,%3,%4};"
                     :: "l"(ad0), "f"(v0[0]), "f"(v0[1]), "f"(v0[2]), "f"(v0[3])
                     : "memory");
        asm volatile("red.global.add.v4.f32 [%0], {%1,%2,%3,%4};"
                     :: "l"(ad0 + 4), "f"(v0[4]), "f"(v0[5]), "f"(v0[6]), "f"(v0[7])
                     : "memory");
        float* ad1 = g_acc + (((size_t)t * NNODES + d1) << 6) + obase;
        asm volatile("red.global.add.v4.f32 [%0], {%1,%2,%3,%4};"
                     :: "l"(ad1), "f"(v1[0]), "f"(v1[1]), "f"(v1[2]), "f"(v1[3])
                     : "memory");
        asm volatile("red.global.add.v4.f32 [%0], {%1,%2,%3,%4};"
                     :: "l"(ad1 + 4), "f"(v1[4]), "f"(v1[5]), "f"(v1[6]), "f"(v1[7])
                     : "memory");
    }

    // reduce stats across the 4 edge-groups of the warp (lane bits 3,4)
#pragma unroll
    for (int o = 0; o < 8; o++) {
        cs[o] += __shfl_xor_sync(0xffffffffu, cs[o], 8);
        cq[o] += __shfl_xor_sync(0xffffffffu, cq[o], 8);
        cs[o] += __shfl_xor_sync(0xffffffffu, cs[o], 16);
        cq[o] += __shfl_xor_sync(0xffffffffu, cq[o], 16);
    }
    if (lane < 8) {       // eg == 0; og == lane
#pragma unroll
        for (int o = 0; o < 8; o++) {
            atomicAdd(&SM_SSUM[obase + o], cs[o]);
            atomicAdd(&SM_SSQ[obase + o], cq[o]);
        }
    }
    __syncthreads();
    if (tid < 64) {
        atomicAdd(&g_sum[t * DIM + tid], SM_SSUM[tid]);
        atomicAdd(&g_sq[t * DIM + tid], SM_SSQ[tid]);
    }
    if (tid < 32) {
#pragma unroll
        for (int j = 0; j < 4; j++)
            atomicAdd(&g_deg[t * NNODES + SM_DSTS[tid * 4 + j]], 1);
    }
}

// ---------------- BN stats finalize ------------------------------------------
__global__ void k_stats(const float* __restrict__ bng, const float* __restrict__ bnb) {
    int i = threadIdx.x;
    if (i < NTYPES * DIM) {
        float mean = g_sum[i] * (1.f / NEDGES);
        float var = g_sq[i] * (1.f / NEDGES) - mean * mean;
        float s = bng[i] * rsqrtf(fmaxf(var, 0.f) + EPSLN);
        g_s[i] = s;
        g_c[i] = bnb[i] - mean * s;
    }
}

// ---------------- final ------------------------------------------------------
__global__ void __launch_bounds__(256) k_final(const float* __restrict__ F,
                                               const float* __restrict__ Wr,
                                               const float* __restrict__ br,
                                               float* __restrict__ out) {
    __shared__ float Ws[64 * 64];
    __shared__ float aT[64 * 72];
    const int tid = threadIdx.x;
    for (int i = tid; i < 1024; i += 256)
        reinterpret_cast<float4*>(Ws)[i] = reinterpret_cast<const float4*>(Wr)[i];

    const int nl = tid >> 2, q = tid & 3;
    const int n = blockIdx.x * 64 + nl;
    float v[16];
#pragma unroll
    for (int i = 0; i < 16; i++) v[i] = 0.f;
    if (n < NNODES) {
#pragma unroll
        for (int t = 0; t < NTYPES; t++) {
            const float4* op = reinterpret_cast<const float4*>(
                g_acc + (((size_t)t * NNODES + n) << 6) + q * 16);
            float dg = (float)g_deg[t * NNODES + n];
#pragma unroll
            for (int i = 0; i < 4; i++) {
                float4 o = op[i];
                int ch = q * 16 + i * 4;
                v[i * 4 + 0] += o.x * g_s[t * DIM + ch + 0] + dg * g_c[t * DIM + ch + 0];
                v[i * 4 + 1] += o.y * g_s[t * DIM + ch + 1] + dg * g_c[t * DIM + ch + 1];
                v[i * 4 + 2] += o.z * g_s[t * DIM + ch + 2] + dg * g_c[t * DIM + ch + 2];
                v[i * 4 + 3] += o.w * g_s[t * DIM + ch + 3] + dg * g_c[t * DIM + ch + 3];
            }
        }
    }
#pragma unroll
    for (int i = 0; i < 16; i++) aT[(q * 16 + i) * 72 + nl] = v[i];
    __syncthreads();

    const int ng = (tid >> 4) << 2;
    const int og = (tid & 15) << 2;
    float acc[4][4] = {};
    const float* apx = &aT[ng];
    const float* wpx = &Ws[og];
#pragma unroll 16
    for (int k = 0; k < 64; k++) {
        float4 av = *reinterpret_cast<const float4*>(apx); apx += 72;
        float4 wv = *reinterpret_cast<const float4*>(wpx); wpx += 64;
        const float aa[4] = {av.x, av.y, av.z, av.w};
        const float wa[4] = {wv.x, wv.y, wv.z, wv.w};
#pragma unroll
        for (int i = 0; i < 4; i++)
#pragma unroll
            for (int j = 0; j < 4; j++) acc[i][j] += aa[i] * wa[j];
    }

    float4 brv = *reinterpret_cast<const float4*>(&br[og]);
    const float bra[4] = {brv.x, brv.y, brv.z, brv.w};
#pragma unroll
    for (int i = 0; i < 4; i++) {
        int nn = blockIdx.x * 64 + ng + i;
        if (nn < NNODES) {
            float4 f = *reinterpret_cast<const float4*>(&F[(size_t)nn * DIM + og]);
            float4 r = make_float4(acc[i][0] + bra[0] + f.x,
                                   acc[i][1] + bra[1] + f.y,
                                   acc[i][2] + bra[2] + f.z,
                                   acc[i][3] + bra[3] + f.w);
            *reinterpret_cast<float4*>(&out[(size_t)nn * DIM + og]) = r;
        }
    }
}

// ---------------- launch ------------------------------------------------------
extern "C" void kernel_launch(void* const* d_in, const int* in_sizes, int n_in,
                              void* d_out, int out_size) {
    const float* F   = (const float*)d_in[0];
    const float* W1  = (const float*)d_in[1];
    const float* b1  = (const float*)d_in[2];
    const float* lng = (const float*)d_in[3];
    const float* lnb = (const float*)d_in[4];
    const float* W2  = (const float*)d_in[5];
    const float* b2  = (const float*)d_in[6];
    const float* bng = (const float*)d_in[7];
    const float* bnb = (const float*)d_in[8];
    const float* Wr  = (const float*)d_in[9];
    const float* br  = (const float*)d_in[10];
    const void*  esrc = d_in[11];
    const void*  edst = d_in[12];

    cudaFuncSetAttribute(k_edge, cudaFuncAttributeMaxDynamicSharedMemorySize,
                         SMEM_BYTES);

    k_detect<<<1, 32>>>((const int*)esrc);
    k_convert<<<(NTYPES * NEDGES + 255) / 256, 256>>>(esrc, edst);
    k_zero<<<2048, 256>>>();

    dim3 gpre((NNODES + 63) / 64, NTYPES, 2);
    k_pre<<<gpre, 256>>>(F, W1, b1);

    dim3 gedge(NEDGES / EPC, NTYPES, 1);
    k_edge<<<gedge, 256, SMEM_BYTES>>>(lng, lnb, W2, b2);

    k_stats<<<1, 256>>>(bng, bnb);

    k_final<<<(NNODES + 63) / 64, 256>>>(F, Wr, br, (float*)d_out);
}

// round 9
// speedup vs baseline: 1.2364x; 1.2364x over previous
#include <cuda_runtime.h>
#include <cstdint>
#include <cstddef>

#define NNODES 50000
#define NEDGES 800000
#define NTYPES 3
#define DIM    64
#define EPSLN  1e-5f

// ---------------- device scratch -------------------------------------------
__device__ __align__(16) float g_A[(size_t)NTYPES * NNODES * DIM];
__device__ __align__(16) float g_B[(size_t)NTYPES * NNODES * DIM];
__device__ __align__(16) float g_acc[(size_t)NTYPES * NNODES * DIM];
__device__ __align__(8)  int2  g_idx[(size_t)NTYPES * NEDGES];   // {src,dst}
__device__ int   g_deg[NTYPES * NNODES];
__device__ float g_sum[NTYPES * DIM];
__device__ float g_sq[NTYPES * DIM];
__device__ float g_s[NTYPES * DIM];
__device__ float g_c[NTYPES * DIM];
__device__ int   g_is64;

// fast ELU: |err| <= ~5e-7 absolute (validated rel_err 8e-7 in R8)
__device__ __forceinline__ float elu(float x) {
    return x > 0.f ? x : (__expf(x) - 1.f);
}

// ---------------- edge-index dtype detection --------------------------------
__global__ void k_detect(const int* __restrict__ e) {
    if (threadIdx.x == 0 && blockIdx.x == 0) {
        int is64 = 1;
        for (int i = 1; i < 256; i += 2)
            if (e[i] != 0) { is64 = 0; break; }
        g_is64 = is64;
    }
}

// ---------------- index conversion: (src,dst) -> packed int2 -----------------
__global__ void __launch_bounds__(256) k_convert(const void* __restrict__ esrc_raw,
                                                 const void* __restrict__ edst_raw) {
    const size_t i = (size_t)blockIdx.x * 256 + threadIdx.x;
    if (i >= (size_t)NTYPES * NEDGES) return;
    int s, d;
    if (g_is64) {
        s = (int)((const long long*)esrc_raw)[i];
        d = (int)((const long long*)edst_raw)[i];
    } else {
        s = ((const int*)esrc_raw)[i];
        d = ((const int*)edst_raw)[i];
    }
    g_idx[i] = make_int2(s, d);
}

// ---------------- zero-init --------------------------------------------------
__global__ void k_zero() {
    size_t stride = (size_t)gridDim.x * blockDim.x;
    size_t i = (size_t)blockIdx.x * blockDim.x + threadIdx.x;
    float4 z = make_float4(0.f, 0.f, 0.f, 0.f);
    float4* a4 = reinterpret_cast<float4*>(g_acc);
    size_t n4 = (size_t)NTYPES * NNODES * DIM / 4;
    for (size_t k = i; k < n4; k += stride) a4[k] = z;
    for (size_t k = i; k < (size_t)NTYPES * NNODES; k += stride) g_deg[k] = 0;
    if (i < NTYPES * DIM) { g_sum[i] = 0.f; g_sq[i] = 0.f; }
}

// ---------------- per-node precompute (vectorized) ---------------------------
__global__ void __launch_bounds__(256) k_pre(const float* __restrict__ F,
                                             const float* __restrict__ W1,
                                             const float* __restrict__ b1) {
    __shared__ float Fs[64 * 68];   // pad 68: 16B-aligned float4 rows
    __shared__ float Ws[64 * 64];
    const int tid = threadIdx.x;
    const int t = blockIdx.y;
    const int half = blockIdx.z;

    const float* Wsrc = W1 + ((size_t)t * 128 + (size_t)half * 64) * 64;
    for (int i = tid; i < 1024; i += 256)
        reinterpret_cast<float4*>(Ws)[i] = reinterpret_cast<const float4*>(Wsrc)[i];

    const int nl = tid >> 2, q = tid & 3;
    const int n = blockIdx.x * 64 + nl;
    {
        const int nc = (n < NNODES) ? n : (NNODES - 1);
        const float4* fr = reinterpret_cast<const float4*>(F + (size_t)nc * DIM + q * 16);
        const float mask = (n < NNODES) ? 1.f : 0.f;
#pragma unroll
        for (int i = 0; i < 4; i++) {
            float4 v = fr[i];
            v.x *= mask; v.y *= mask; v.z *= mask; v.w *= mask;
            *reinterpret_cast<float4*>(&Fs[nl * 68 + q * 16 + i * 4]) = v;
        }
    }
    __syncthreads();

    const int ng = (tid >> 4) << 2;
    const int og = (tid & 15) << 2;
    float acc[4][4] = {};
#pragma unroll 16
    for (int k = 0; k < 64; k++) {
        float a[4];
#pragma unroll
        for (int i = 0; i < 4; i++) a[i] = Fs[(ng + i) * 68 + k];
        float4 w = *reinterpret_cast<const float4*>(&Ws[k * 64 + og]);
        const float wa[4] = {w.x, w.y, w.z, w.w};
#pragma unroll
        for (int i = 0; i < 4; i++)
#pragma unroll
            for (int j = 0; j < 4; j++) acc[i][j] += a[i] * wa[j];
    }

    float bb[4] = {0.f, 0.f, 0.f, 0.f};
    if (half == 0) {
        float4 bv = *reinterpret_cast<const float4*>(&b1[t * DIM + og]);
        bb[0] = bv.x; bb[1] = bv.y; bb[2] = bv.z; bb[3] = bv.w;
    }
    float* dst = (half ? g_B : g_A);
#pragma unroll
    for (int i = 0; i < 4; i++) {
        int nn = blockIdx.x * 64 + ng + i;
        if (nn < NNODES) {
            float4 r = make_float4(acc[i][0] + bb[0], acc[i][1] + bb[1],
                                   acc[i][2] + bb[2], acc[i][3] + bb[3]);
            *reinterpret_cast<float4*>(
                &dst[(((size_t)t * NNODES + nn) << 6) + og]) = r;
        }
    }
}

// ---------------- main edge kernel (R2 architecture + micro-wins) ------------
// 64 edges per CTA (12500 CTAs x 3 types), 256 threads, static smem ~37KB.
__global__ void __launch_bounds__(256) k_edge(const float* __restrict__ lng,
                                              const float* __restrict__ lnb,
                                              const float* __restrict__ W2,
                                              const float* __restrict__ b2) {
    __shared__ float W2s[64 * 64];
    __shared__ float hnT[64 * 72];      // [ch][edge], padded
    __shared__ float sSum[64], sSq[64];
    __shared__ int   dsts[64];
    __shared__ float s_lng[64], s_lnb[64], s_b2[64];

    const int tid = threadIdx.x;
    const int t = blockIdx.y;

    const float* W2p = W2 + (size_t)t * 64 * 64;
    for (int i = tid; i < 1024; i += 256)
        reinterpret_cast<float4*>(W2s)[i] = reinterpret_cast<const float4*>(W2p)[i];
    if (tid < 64) {
        s_lng[tid] = lng[t * DIM + tid];
        s_lnb[tid] = lnb[t * DIM + tid];
        s_b2[tid]  = b2[t * DIM + tid];
        sSum[tid] = 0.f; sSq[tid] = 0.f;
    }
    __syncthreads();

    const int el = tid >> 2, q = tid & 3;
    const size_t ge = (size_t)blockIdx.x * 64 + el;     // 12500*64 == NEDGES, no tail
    const int2 sd = g_idx[(size_t)t * NEDGES + ge];
    const int src = sd.x, dst = sd.y;

    float h[16];
    float sm = 0.f, sq = 0.f;
    {
        const float4* ap = reinterpret_cast<const float4*>(
            g_A + (((size_t)t * NNODES + (size_t)src) << 6) + q * 16);
        const float4* bp = reinterpret_cast<const float4*>(
            g_B + (((size_t)t * NNODES + (size_t)dst) << 6) + q * 16);
        float4 av[4], bv[4];
#pragma unroll
        for (int i = 0; i < 4; i++) av[i] = ap[i];
#pragma unroll
        for (int i = 0; i < 4; i++) bv[i] = bp[i];
#pragma unroll
        for (int i = 0; i < 4; i++) {
            float v0 = elu(av[i].x + bv[i].x), v1 = elu(av[i].y + bv[i].y);
            float v2 = elu(av[i].z + bv[i].z), v3 = elu(av[i].w + bv[i].w);
            h[i * 4 + 0] = v0; h[i * 4 + 1] = v1;
            h[i * 4 + 2] = v2; h[i * 4 + 3] = v3;
            sm += v0 + v1 + v2 + v3;
            sq += v0 * v0 + v1 * v1 + v2 * v2 + v3 * v3;
        }
    }
    // LayerNorm stats across the 4 threads of this edge
    sm += __shfl_xor_sync(0xffffffffu, sm, 1);
    sq += __shfl_xor_sync(0xffffffffu, sq, 1);
    sm += __shfl_xor_sync(0xffffffffu, sm, 2);
    sq += __shfl_xor_sync(0xffffffffu, sq, 2);
    const float mu = sm * (1.f / 64.f);
    const float var = sq * (1.f / 64.f) - mu * mu;
    const float rstd = rsqrtf(var + EPSLN);
#pragma unroll
    for (int i = 0; i < 16; i++) {
        int ch = q * 16 + i;
        hnT[ch * 72 + el] = (h[i] - mu) * rstd * s_lng[ch] + s_lnb[ch];
    }
    if (q == 0) dsts[el] = dst;
    __syncthreads();

    // Phase B: P[64e x 64ch] = hn @ W2, 4x4 micro-tiles
    const int eg = (tid >> 4) << 2;
    const int og = (tid & 15) << 2;
    float acc[4][4] = {};
    const float* hp = &hnT[eg];
    const float* wp = &W2s[og];
#pragma unroll 16
    for (int m = 0; m < 64; m++) {
        float4 hv = *reinterpret_cast<const float4*>(hp); hp += 72;
        float4 wv = *reinterpret_cast<const float4*>(wp); wp += 64;
        const float ha[4] = {hv.x, hv.y, hv.z, hv.w};
        const float wa[4] = {wv.x, wv.y, wv.z, wv.w};
#pragma unroll
        for (int i = 0; i < 4; i++)
#pragma unroll
            for (int j = 0; j < 4; j++) acc[i][j] += ha[i] * wa[j];
    }

    // Phase C: ELU + scatter + stats
    float4 bv = *reinterpret_cast<const float4*>(&s_b2[og]);
    const float ba[4] = {bv.x, bv.y, bv.z, bv.w};
    float cs[4] = {0.f, 0.f, 0.f, 0.f}, cq[4] = {0.f, 0.f, 0.f, 0.f};
#pragma unroll
    for (int i = 0; i < 4; i++) {
        int d = dsts[eg + i];
        float p0 = elu(acc[i][0] + ba[0]);
        float p1 = elu(acc[i][1] + ba[1]);
        float p2 = elu(acc[i][2] + ba[2]);
        float p3 = elu(acc[i][3] + ba[3]);
        float* addr = g_acc + (((size_t)t * NNODES + d) << 6) + og;
        asm volatile("red.global.add.v4.f32 [%0], {%1,%2,%3,%4};"
                     :: "l"(addr), "f"(p0), "f"(p1), "f"(p2), "f"(p3)
                     : "memory");
        cs[0] += p0; cs[1] += p1; cs[2] += p2; cs[3] += p3;
        cq[0] += p0 * p0; cq[1] += p1 * p1;
        cq[2] += p2 * p2; cq[3] += p3 * p3;
    }
    if ((tid & 15) == 0) {
#pragma unroll
        for (int i = 0; i < 4; i++)
            atomicAdd(&g_deg[t * NNODES + dsts[eg + i]], 1);
    }
#pragma unroll
    for (int j = 0; j < 4; j++) {
        cs[j] += __shfl_xor_sync(0xffffffffu, cs[j], 16);
        cq[j] += __shfl_xor_sync(0xffffffffu, cq[j], 16);
    }
    if ((tid & 31) < 16) {
#pragma unroll
        for (int j = 0; j < 4; j++) {
            atomicAdd(&sSum[og + j], cs[j]);
            atomicAdd(&sSq[og + j], cq[j]);
        }
    }
    __syncthreads();
    if (tid < 64) {
        atomicAdd(&g_sum[t * DIM + tid], sSum[tid]);
        atomicAdd(&g_sq[t * DIM + tid], sSq[tid]);
    }
}

// ---------------- BN stats finalize ------------------------------------------
__global__ void k_stats(const float* __restrict__ bng, const float* __restrict__ bnb) {
    int i = threadIdx.x;
    if (i < NTYPES * DIM) {
        float mean = g_sum[i] * (1.f / NEDGES);
        float var = g_sq[i] * (1.f / NEDGES) - mean * mean;
        float s = bng[i] * rsqrtf(fmaxf(var, 0.f) + EPSLN);
        g_s[i] = s;
        g_c[i] = bnb[i] - mean * s;
    }
}

// ---------------- final ------------------------------------------------------
__global__ void __launch_bounds__(256) k_final(const float* __restrict__ F,
                                               const float* __restrict__ Wr,
                                               const float* __restrict__ br,
                                               float* __restrict__ out) {
    __shared__ float Ws[64 * 64];
    __shared__ float aT[64 * 72];
    const int tid = threadIdx.x;
    for (int i = tid; i < 1024; i += 256)
        reinterpret_cast<float4*>(Ws)[i] = reinterpret_cast<const float4*>(Wr)[i];

    const int nl = tid >> 2, q = tid & 3;
    const int n = blockIdx.x * 64 + nl;
    float v[16];
#pragma unroll
    for (int i = 0; i < 16; i++) v[i] = 0.f;
    if (n < NNODES) {
#pragma unroll
        for (int t = 0; t < NTYPES; t++) {
            const float4* op = reinterpret_cast<const float4*>(
                g_acc + (((size_t)t * NNODES + n) << 6) + q * 16);
            float dg = (float)g_deg[t * NNODES + n];
#pragma unroll
            for (int i = 0; i < 4; i++) {
                float4 o = op[i];
                int ch = q * 16 + i * 4;
                v[i * 4 + 0] += o.x * g_s[t * DIM + ch + 0] + dg * g_c[t * DIM + ch + 0];
                v[i * 4 + 1] += o.y * g_s[t * DIM + ch + 1] + dg * g_c[t * DIM + ch + 1];
                v[i * 4 + 2] += o.z * g_s[t * DIM + ch + 2] + dg * g_c[t * DIM + ch + 2];
                v[i * 4 + 3] += o.w * g_s[t * DIM + ch + 3] + dg * g_c[t * DIM + ch + 3];
            }
        }
    }
#pragma unroll
    for (int i = 0; i < 16; i++) aT[(q * 16 + i) * 72 + nl] = v[i];
    __syncthreads();

    const int ng = (tid >> 4) << 2;
    const int og = (tid & 15) << 2;
    float acc[4][4] = {};
    const float* apx = &aT[ng];
    const float* wpx = &Ws[og];
#pragma unroll 16
    for (int k = 0; k < 64; k++) {
        float4 av = *reinterpret_cast<const float4*>(apx); apx += 72;
        float4 wv = *reinterpret_cast<const float4*>(wpx); wpx += 64;
        const float aa[4] = {av.x, av.y, av.z, av.w};
        const float wa[4] = {wv.x, wv.y, wv.z, wv.w};
#pragma unroll
        for (int i = 0; i < 4; i++)
#pragma unroll
            for (int j = 0; j < 4; j++) acc[i][j] += aa[i] * wa[j];
    }

    float4 brv = *reinterpret_cast<const float4*>(&br[og]);
    const float bra[4] = {brv.x, brv.y, brv.z, brv.w};
#pragma unroll
    for (int i = 0; i < 4; i++) {
        int nn = blockIdx.x * 64 + ng + i;
        if (nn < NNODES) {
            float4 f = *reinterpret_cast<const float4*>(&F[(size_t)nn * DIM + og]);
            float4 r = make_float4(acc[i][0] + bra[0] + f.x,
                                   acc[i][1] + bra[1] + f.y,
                                   acc[i][2] + bra[2] + f.z,
                                   acc[i][3] + bra[3] + f.w);
            *reinterpret_cast<float4*>(&out[(size_t)nn * DIM + og]) = r;
        }
    }
}

// ---------------- launch ------------------------------------------------------
extern "C" void kernel_launch(void* const* d_in, const int* in_sizes, int n_in,
                              void* d_out, int out_size) {
    const float* F   = (const float*)d_in[0];
    const float* W1  = (const float*)d_in[1];
    const float* b1  = (const float*)d_in[2];
    const float* lng = (const float*)d_in[3];
    const float* lnb = (const float*)d_in[4];
    const float* W2  = (const float*)d_in[5];
    const float* b2  = (const float*)d_in[6];
    const float* bng = (const float*)d_in[7];
    const float* bnb = (const float*)d_in[8];
    const float* Wr  = (const float*)d_in[9];
    const float* br  = (const float*)d_in[10];
    const void*  esrc = d_in[11];
    const void*  edst = d_in[12];

    k_detect<<<1, 32>>>((const int*)esrc);
    k_convert<<<(NTYPES * NEDGES + 255) / 256, 256>>>(esrc, edst);
    k_zero<<<2048, 256>>>();

    dim3 gpre((NNODES + 63) / 64, NTYPES, 2);
    k_pre<<<gpre, 256>>>(F, W1, b1);

    dim3 gedge(NEDGES / 64, NTYPES, 1);
    k_edge<<<gedge, 256>>>(lng, lnb, W2, b2);

    k_stats<<<1, 256>>>(bng, bnb);

    k_final<<<(NNODES + 63) / 64, 256>>>(F, Wr, br, (float*)d_out);
}